// round 8
// baseline (speedup 1.0000x reference)
#include <cuda_runtime.h>

#define BATCH 4
#define NPTS  4096
#define KPN   512
#define KNN   32

#define TPB   256
#define BSL   128             // refs staged per block (loop length)
#define NBS   (NPTS / BSL)    // 32
#define ATILE 2048            // queries per block (8 per thread)
#define NAT   (NPTS / ATILE)  // 2
#define NBLK  (BATCH * NAT * NBS)  // 256 blocks (all co-resident)
#define INFV  3.0e38f

// Encoded global mins: [0,16384) row (per-tgt-point), [16384,32768) col
// (per-src-point). Descending encoding => atomicMax == float-min, 0 == empty.
// Zero at module load; finalize phase re-zeros every entry each launch.
__device__ unsigned g_minbits[2 * BATCH * NPTS];
__device__ unsigned g_arrive;   // grid-sync arrival counter (0 at load & after each launch)
__device__ unsigned g_done;     // finalize-done counter   (0 at load & after each launch)

__device__ __forceinline__ unsigned enc_desc(float f) {
    unsigned u = __float_as_uint(f);
    return (u & 0x80000000u) ? u : ~(u | 0x80000000u);
}
__device__ __forceinline__ float dec_desc(unsigned e) {
    unsigned s = ~e;
    unsigned u = (s & 0x80000000u) ? (s ^ 0x80000000u) : ~s;
    return __uint_as_float(u);
}

// Packed f32x2 ops (sm_103a, PTX-only)
__device__ __forceinline__ float2 ffma2(float2 a, float2 b, float2 c) {
    float2 d;
    asm("fma.rn.f32x2 %0, %1, %2, %3;"
        : "=l"(*reinterpret_cast<unsigned long long*>(&d))
        : "l"(*reinterpret_cast<const unsigned long long*>(&a)),
          "l"(*reinterpret_cast<const unsigned long long*>(&b)),
          "l"(*reinterpret_cast<const unsigned long long*>(&c)));
    return d;
}
__device__ __forceinline__ float2 fadd2(float2 a, float2 b) {
    float2 d;
    asm("add.rn.f32x2 %0, %1, %2;"
        : "=l"(*reinterpret_cast<unsigned long long*>(&d))
        : "l"(*reinterpret_cast<const unsigned long long*>(&a)),
          "l"(*reinterpret_cast<const unsigned long long*>(&b)));
    return d;
}

__device__ __forceinline__ float block_reduce_sum(float v, float* sh) {
    int lane = threadIdx.x & 31;
    int wid  = threadIdx.x >> 5;
    #pragma unroll
    for (int o = 16; o; o >>= 1) v += __shfl_down_sync(0xffffffffu, v, o);
    if (lane == 0) sh[wid] = v;
    __syncthreads();
    if (wid == 0) {
        v = (lane < (TPB >> 5)) ? sh[lane] : 0.0f;
        #pragma unroll
        for (int o = 16; o; o >>= 1) v += __shfl_down_sync(0xffffffffu, v, o);
    }
    return v;
}

// ---------------------------------------------------------------------------
// Single fused kernel:
//   Phase 1: tile distance pass (full dists once; row mins in regs, col mins
//            in per-warp smem), fold into g_minbits via encoded RED.MAX.
//   Phase 2: per-block nbh partial (knn L2 + keypoint loss) — overlaps
//            straggler blocks still in phase 1.
//   Grid sync (arrive counter + nanosleep spin; 256 blocks co-resident).
//   Phase 3: coalesced finalize — decode mins, huber, sum; reset all state.
// ---------------------------------------------------------------------------
__global__ void __launch_bounds__(TPB) loss_kernel(const float* __restrict__ A,
                                                   const float* __restrict__ B,
                                                   const float* __restrict__ sk,
                                                   const float* __restrict__ tk,
                                                   const float* __restrict__ Rot,
                                                   const float* __restrict__ Tr,
                                                   const float* __restrict__ sknn,
                                                   const float* __restrict__ tknn,
                                                   float* __restrict__ out) {
    __shared__ float4 sB1[BSL];        // (bx,bx,by,by)
    __shared__ float4 sB2[BSL];        // (bz,bz,bn,bn)
    __shared__ float  cmin[8][BSL];    // per-warp col partial mins
    __shared__ float  sred[32];        // reduction scratch

    int bid = blockIdx.x;
    int bs  = bid & (NBS - 1);         // B slice 0..31
    int at  = (bid >> 5) & (NAT - 1);  // A tile 0..1
    int b   = bid >> 6;                // batch
    int t   = threadIdx.x;
    int w   = t >> 5;

    if (bid == 0 && t == 0) { out[0] = 0.0f; out[1] = 0.0f; }

    const float* Ab = A + b * 3 * NPTS;  // gts (tgt)
    const float* Bb = B + b * 3 * NPTS;  // preds (src_transformed)

    // ---- Phase 1: distances ----
    if (t < BSL) {
        int j = bs * BSL + t;
        float bx = Bb[j], by = Bb[NPTS + j], bz = Bb[2 * NPTS + j];
        float bn = fmaf(bx, bx, fmaf(by, by, bz * bz));
        sB1[t] = make_float4(bx, bx, by, by);
        sB2[t] = make_float4(bz, bz, bn, bn);
    }
    for (int idx = t; idx < 8 * BSL; idx += TPB) (&cmin[0][0])[idx] = INFV;
    __syncthreads();

    float2 qx[4], qy[4], qz[4], qn[4];
    float  m[8];
    int i0 = at * ATILE + t;
    #pragma unroll
    for (int jp = 0; jp < 4; jp++) {
        int ia = i0 + (2 * jp) * TPB;
        int ic = i0 + (2 * jp + 1) * TPB;
        float ax = Ab[ia], ay = Ab[NPTS + ia], az = Ab[2 * NPTS + ia];
        float cx = Ab[ic], cy = Ab[NPTS + ic], cz = Ab[2 * NPTS + ic];
        float na = fmaf(ax, ax, fmaf(ay, ay, az * az));
        float nc = fmaf(cx, cx, fmaf(cy, cy, cz * cz));
        qx[jp] = make_float2(-2.0f * ax, -2.0f * cx);
        qy[jp] = make_float2(-2.0f * ay, -2.0f * cy);
        qz[jp] = make_float2(-2.0f * az, -2.0f * cz);
        qn[jp] = make_float2(na, nc);
        m[2 * jp] = INFV; m[2 * jp + 1] = INFV;
    }

    #pragma unroll 4
    for (int i = 0; i < BSL; i++) {
        int r = (t + i) & (BSL - 1);   // skewed: lanes hit distinct refs/banks
        float4 b1 = sB1[r];
        float4 b2 = sB2[r];
        float2 rx = make_float2(b1.x, b1.y);
        float2 ry = make_float2(b1.z, b1.w);
        float2 rz = make_float2(b2.x, b2.y);
        float2 rn = make_float2(b2.z, b2.w);

        float p[4];
        #pragma unroll
        for (int jp = 0; jp < 4; jp++) {
            float2 bias = fadd2(qn[jp], rn);
            float2 d2 = ffma2(qx[jp], rx, ffma2(qy[jp], ry, ffma2(qz[jp], rz, bias)));
            m[2 * jp]     = fminf(m[2 * jp],     d2.x);
            m[2 * jp + 1] = fminf(m[2 * jp + 1], d2.y);
            p[jp] = fminf(d2.x, d2.y);
        }
        float v = fminf(fminf(p[0], p[1]), fminf(p[2], p[3]));
        cmin[w][r] = fminf(cmin[w][r], v);
    }
    __syncthreads();

    unsigned* rowm = g_minbits + b * NPTS;
    #pragma unroll
    for (int u = 0; u < 8; u++)
        atomicMax(&rowm[i0 + u * TPB], enc_desc(m[u]));

    if (t < BSL) {
        float cv = cmin[0][t];
        #pragma unroll
        for (int ww = 1; ww < 8; ww++) cv = fminf(cv, cmin[ww][t]);
        atomicMax(&g_minbits[BATCH * NPTS + b * NPTS + bs * BSL + t], enc_desc(cv));
    }

    // ---- Phase 2: nbh partial (overlaps other blocks' phase 1) ----
    int gi = bid * TPB + t;            // 0..65535
    float acc = 0.0f;
    const int TOT4 = BATCH * 3 * KPN * KNN / 4;  // 49152
    if (gi < TOT4) {
        const float4* s4 = (const float4*)sknn;
        const float4* t4 = (const float4*)tknn;
        float4 a0 = s4[gi], b0 = t4[gi];
        float d0 = a0.x - b0.x, d1 = a0.y - b0.y, d2 = a0.z - b0.z, d3 = a0.w - b0.w;
        acc = fmaf(d0, d0, fmaf(d1, d1, fmaf(d2, d2, d3 * d3)));
    }
    acc *= (1.0f / (float)KNN);
    if (gi < BATCH * KPN) {
        int kb = gi >> 9;
        int p  = gi & (KPN - 1);
        const float* Rb  = Rot + kb * 9;
        const float* tb  = Tr + kb * 3;
        const float* skb = sk + kb * 3 * KPN;
        const float* tkb = tk + kb * 3 * KPN;
        float px = skb[p], py = skb[KPN + p], pz = skb[2 * KPN + p];
        #pragma unroll
        for (int cd = 0; cd < 3; cd++) {
            float wv = fmaf(Rb[cd * 3 + 0], px,
                       fmaf(Rb[cd * 3 + 1], py,
                       fmaf(Rb[cd * 3 + 2], pz, tb[cd])))
                       - tkb[cd * KPN + p];
            acc = fmaf(wv, wv, acc);
        }
    }
    float s_nbh = block_reduce_sum(acc, sred);  // valid in thread 0

    // ---- Grid sync ----
    __threadfence();
    __syncthreads();
    if (t == 0) {
        atomicAdd(&g_arrive, 1u);
        while (*((volatile unsigned*)&g_arrive) < (unsigned)NBLK) __nanosleep(64);
    }
    __syncthreads();
    __threadfence();

    // ---- Phase 3: finalize (128 entries per block, coalesced) ----
    float h = 0.0f;
    if (t < 128) {
        int idx = bid * 128 + t;       // 0..32767
        unsigned e = g_minbits[idx];
        g_minbits[idx] = 0;            // reset for next replay
        float d = dec_desc(e);
        const float c = 0.01f;
        h = (d < c) ? (0.5f * d * d) : fmaf(c, d, -0.5f * c * c);
    }
    float s_gal = block_reduce_sum(h, sred);

    if (t == 0) {
        atomicAdd(&out[0], s_nbh);
        atomicAdd(&out[1], s_gal);
        __threadfence();
        unsigned dcnt = atomicAdd(&g_done, 1u);
        if (dcnt == (unsigned)(NBLK - 1)) {  // last block: reset sync state
            g_arrive = 0u;
            g_done   = 0u;
        }
    }
}

// ---------------------------------------------------------------------------
extern "C" void kernel_launch(void* const* d_in, const int* in_sizes, int n_in,
                              void* d_out, int out_size) {
    const float* src_kp  = (const float*)d_in[0];  // (B,3,KP)
    const float* tgt_kp  = (const float*)d_in[1];  // (B,3,KP)
    const float* rot     = (const float*)d_in[2];  // (B,3,3)
    const float* tra     = (const float*)d_in[3];  // (B,3)
    const float* src_knn = (const float*)d_in[4];  // (B,3,KP,K)
    const float* tgt_knn = (const float*)d_in[5];  // (B,3,KP,K)
    // d_in[6] = k (constant 32, hardcoded)
    const float* src_tr  = (const float*)d_in[7];  // (B,3,N) preds
    const float* tgt     = (const float*)d_in[8];  // (B,3,N) gts
    float* out = (float*)d_out;                    // out[0]=nbh, out[1]=gal

    loss_kernel<<<NBLK, TPB>>>(tgt, src_tr, src_kp, tgt_kp, rot, tra,
                               src_knn, tgt_knn, out);
}